// round 1
// baseline (speedup 1.0000x reference)
#include <cuda_runtime.h>
#include <cstdint>

#define B_DIM 32
#define S_LEN 2048
#define I_DIM 256
#define H_DIM 256

// ---------------------------------------------------------------------------
// f32x2 packed-FMA helpers (sm_100+ PTX; 2 MACs per issue slot)
// ---------------------------------------------------------------------------
__device__ __forceinline__ unsigned long long ffma2(unsigned long long a,
                                                    unsigned long long b,
                                                    unsigned long long c) {
    unsigned long long d;
    asm("fma.rn.f32x2 %0, %1, %2, %3;" : "=l"(d) : "l"(a), "l"(b), "l"(c));
    return d;
}
__device__ __forceinline__ unsigned long long pack2(float x, float y) {
    unsigned long long d;
    asm("mov.b64 %0, {%1, %2};" : "=l"(d) : "f"(x), "f"(y));
    return d;
}
__device__ __forceinline__ float2 unpack2(unsigned long long v) {
    float2 r;
    asm("mov.b64 {%0, %1}, %2;" : "=f"(r.x), "=f"(r.y) : "l"(v));
    return r;
}
__device__ __forceinline__ uint32_t smem_u32(const void* p) {
    uint32_t a;
    asm("{ .reg .u64 t; cvta.to.shared.u64 t, %1; cvt.u32.u64 %0, t; }"
        : "=r"(a) : "l"(p));
    return a;
}
__device__ __forceinline__ uint32_t mapa_u32(uint32_t a, uint32_t rank) {
    uint32_t d;
    asm("mapa.shared::cluster.u32 %0, %1, %2;" : "=r"(d) : "r"(a), "r"(rank));
    return d;
}

// ---------------------------------------------------------------------------
// Kernel 1: xw[b,s,h] = x[b,s,:] . Wx_w[h,:] + Wx_b[h]
// Written into the outputs region of d_out (recurrence overwrites in place).
// Tiling: 128(M) x 128(N) x 16(K), 256 threads, 8x8 per thread, f32x2 inner.
// ---------------------------------------------------------------------------
__global__ __launch_bounds__(256, 2)
void xw_gemm_kernel(const float* __restrict__ A, const float* __restrict__ W,
                    const float* __restrict__ bias, float* __restrict__ C) {
    __shared__ __align__(16) float As[16][128];
    __shared__ __align__(16) float Bs[16][128];

    const int tid = threadIdx.x;
    const int tx = tid & 15;        // N direction (8 cols each)
    const int ty = tid >> 4;        // M direction (8 rows each)
    const long bm = (long)blockIdx.x * 128;
    const long bn = (long)blockIdx.y * 128;

    const float* Ab = A + bm * I_DIM;
    const float* Wb = W + bn * I_DIM;

    unsigned long long acc[8][4];
#pragma unroll
    for (int i = 0; i < 8; i++)
#pragma unroll
        for (int j = 0; j < 4; j++) acc[i][j] = 0ull;

    for (int k0 = 0; k0 < I_DIM; k0 += 16) {
#pragma unroll
        for (int f = tid; f < 512; f += 256) {
            int row = f >> 2, kq = f & 3;
            float4 va = *(const float4*)(Ab + (long)row * I_DIM + k0 + kq * 4);
            As[kq * 4 + 0][row] = va.x; As[kq * 4 + 1][row] = va.y;
            As[kq * 4 + 2][row] = va.z; As[kq * 4 + 3][row] = va.w;
            float4 vw = *(const float4*)(Wb + (long)row * I_DIM + k0 + kq * 4);
            Bs[kq * 4 + 0][row] = vw.x; Bs[kq * 4 + 1][row] = vw.y;
            Bs[kq * 4 + 2][row] = vw.z; Bs[kq * 4 + 3][row] = vw.w;
        }
        __syncthreads();
#pragma unroll
        for (int k = 0; k < 16; k++) {
            const float4* As4 = (const float4*)&As[k][0];
            const ulonglong2* Bs2 = (const ulonglong2*)&Bs[k][0];
            float4 a0 = As4[ty * 2], a1 = As4[ty * 2 + 1];
            ulonglong2 bA = Bs2[tx * 2], bB = Bs2[tx * 2 + 1];
            unsigned long long bp[4] = {bA.x, bA.y, bB.x, bB.y};
            float av[8] = {a0.x, a0.y, a0.z, a0.w, a1.x, a1.y, a1.z, a1.w};
#pragma unroll
            for (int i = 0; i < 8; i++) {
                unsigned long long ap = pack2(av[i], av[i]);
#pragma unroll
                for (int j = 0; j < 4; j++) acc[i][j] = ffma2(ap, bp[j], acc[i][j]);
            }
        }
        __syncthreads();
    }

    float bv[8];
#pragma unroll
    for (int j = 0; j < 8; j++) bv[j] = bias[bn + tx * 8 + j];
#pragma unroll
    for (int i = 0; i < 8; i++) {
        long m = bm + ty * 8 + i;
        float* Crow = C + m * (long)H_DIM + bn + tx * 8;
        float2 c0 = unpack2(acc[i][0]), c1 = unpack2(acc[i][1]);
        float2 c2 = unpack2(acc[i][2]), c3 = unpack2(acc[i][3]);
        float4 o0 = make_float4(c0.x + bv[0], c0.y + bv[1], c1.x + bv[2], c1.y + bv[3]);
        float4 o1 = make_float4(c2.x + bv[4], c2.y + bv[5], c3.x + bv[6], c3.y + bv[7]);
        *(float4*)(Crow) = o0;
        *(float4*)(Crow + 4) = o1;
    }
}

// ---------------------------------------------------------------------------
// Kernel 2: recurrence h_{t+1} = tanh(xw_t + Wh h_t), one 2-CTA cluster per
// batch row. CTA rank r owns output columns j in [128r, 128r+128).
// Thread (jl, kc): j = 128r + jl, k-chunk kc*64..kc*64+63; 64 Wh weights live
// permanently in registers (bank-stagger-rotated). Per step: 32 f32x2 FMAs,
// shfl reduce over 4 kc lanes, tanh, write h to local + peer smem (DSMEM),
// one cluster barrier. Double-buffered h -> single barrier per step.
// ---------------------------------------------------------------------------
__global__ __launch_bounds__(512, 1) __cluster_dims__(2, 1, 1)
void srnn_recur_kernel(const float* __restrict__ Wh, float* __restrict__ out) {
    __shared__ __align__(16) float hbuf[2][H_DIM];

    const int rank = blockIdx.x;     // cluster rank (cluster dim x = 2)
    const int row = blockIdx.y;      // batch row
    const int t = threadIdx.x;
    const int jl = t >> 2;           // 0..127
    const int kc = t & 3;            // 0..3 (k-chunk)
    const int jg = rank * 128 + jl;  // global output column

    // Load 64 weights into registers, rotated by 2*kc float4-slots so the 4
    // kc lanes in a warp read disjoint smem banks in the hot loop.
    unsigned long long wlo[16], whi[16];
    const float* wrow = Wh + (long)jg * H_DIM + kc * 64;
#pragma unroll
    for (int u = 0; u < 16; u++) {
        int i = (u + 2 * kc) & 15;
        ulonglong2 w = *(const ulonglong2*)(wrow + i * 4);
        wlo[u] = w.x;
        whi[u] = w.y;
    }

    if (t < H_DIM) hbuf[0][t] = 0.0f;  // h0 = 0
    __syncthreads();

    // Peer-CTA addresses of my jg slot in both buffers.
    uint32_t ra0 = mapa_u32(smem_u32(&hbuf[0][jg]), rank ^ 1);
    uint32_t ra1 = mapa_u32(smem_u32(&hbuf[1][jg]), rank ^ 1);

    asm volatile("barrier.cluster.arrive.aligned;" ::: "memory");
    asm volatile("barrier.cluster.wait.aligned;" ::: "memory");

    float* xwp = out + (long)row * S_LEN * H_DIM + jg;
    float xw_next = (kc == 0) ? xwp[0] : 0.0f;

    int p = 0;
    for (int step = 0; step < S_LEN; step++) {
        float xw_cur = xw_next;
        if (kc == 0 && step + 1 < S_LEN)
            xw_next = xwp[(long)(step + 1) * H_DIM];  // prefetch next step

        const ulonglong2* h2 = (const ulonglong2*)&hbuf[p][0];
        unsigned long long acc0 = 0ull, acc1 = 0ull;
#pragma unroll
        for (int u = 0; u < 16; u++) {
            int i = kc * 16 + ((u + 2 * kc) & 15);  // staggered, conflict-free
            ulonglong2 hv = h2[i];
            acc0 = ffma2(hv.x, wlo[u], acc0);
            acc1 = ffma2(hv.y, whi[u], acc1);
        }
        float2 f0 = unpack2(acc0), f1 = unpack2(acc1);
        float s = (f0.x + f0.y) + (f1.x + f1.y);
        s += __shfl_xor_sync(0xffffffffu, s, 1);
        s += __shfl_xor_sync(0xffffffffu, s, 2);

        if (kc == 0) {
            float v = tanhf(s + xw_cur);
            hbuf[p ^ 1][jg] = v;
            uint32_t raddr = (p == 0) ? ra1 : ra0;
            asm volatile("st.shared::cluster.f32 [%0], %1;" :: "r"(raddr), "f"(v));
            xwp[(long)step * H_DIM] = v;  // overwrite xw with output (in place)
            if (step == S_LEN - 1)
                out[(long)B_DIM * S_LEN * H_DIM + (long)row * H_DIM + jg] = v;
        }

        // release local+DSMEM writes, acquire peer's writes
        asm volatile("barrier.cluster.arrive.aligned;" ::: "memory");
        asm volatile("barrier.cluster.wait.aligned;" ::: "memory");
        p ^= 1;
    }
}

// ---------------------------------------------------------------------------
// Launch
// ---------------------------------------------------------------------------
extern "C" void kernel_launch(void* const* d_in, const int* in_sizes, int n_in,
                              void* d_out, int out_size) {
    const float* x    = (const float*)d_in[0];  // [B,S,I]
    const float* Wx_w = (const float*)d_in[1];  // [H,I]
    const float* Wx_b = (const float*)d_in[2];  // [H]
    const float* Wh_w = (const float*)d_in[3];  // [H,H]
    float* out = (float*)d_out;                 // [B,S,H] outputs ++ [B,H] h_last

    // Phase 1: xw into the outputs region.
    dim3 g1((B_DIM * S_LEN) / 128, H_DIM / 128);
    xw_gemm_kernel<<<g1, 256>>>(x, Wx_w, Wx_b, out);

    // Phase 2: sequential recurrence, one 2-CTA cluster per batch row.
    dim3 g2(2, B_DIM);
    srnn_recur_kernel<<<g2, 512>>>(Wh_w, out);
}

// round 2
// speedup vs baseline: 2.3765x; 2.3765x over previous
#include <cuda_runtime.h>
#include <cstdint>

#define B_DIM 32
#define S_LEN 2048
#define I_DIM 256
#define H_DIM 256

// ---------------------------------------------------------------------------
// helpers
// ---------------------------------------------------------------------------
__device__ __forceinline__ unsigned long long ffma2(unsigned long long a,
                                                    unsigned long long b,
                                                    unsigned long long c) {
    unsigned long long d;
    asm("fma.rn.f32x2 %0, %1, %2, %3;" : "=l"(d) : "l"(a), "l"(b), "l"(c));
    return d;
}
__device__ __forceinline__ unsigned long long pack2(float x, float y) {
    unsigned long long d;
    asm("mov.b64 %0, {%1, %2};" : "=l"(d) : "f"(x), "f"(y));
    return d;
}
__device__ __forceinline__ float2 unpack2(unsigned long long v) {
    float2 r;
    asm("mov.b64 {%0, %1}, %2;" : "=f"(r.x), "=f"(r.y) : "l"(v));
    return r;
}
__device__ __forceinline__ uint32_t smem_u32(const void* p) {
    uint32_t a;
    asm("{ .reg .u64 t; cvta.to.shared.u64 t, %1; cvt.u32.u64 %0, t; }"
        : "=r"(a) : "l"(p));
    return a;
}
__device__ __forceinline__ uint32_t mapa_u32(uint32_t a, uint32_t rank) {
    uint32_t d;
    asm("mapa.shared::cluster.u32 %0, %1, %2;" : "=r"(d) : "r"(a), "r"(rank));
    return d;
}
__device__ __forceinline__ void mbar_init(uint32_t mbar, uint32_t count) {
    asm volatile("mbarrier.init.shared.b64 [%0], %1;" :: "r"(mbar), "r"(count) : "memory");
}
__device__ __forceinline__ void mbar_arrive(uint32_t mbar) {
    asm volatile("mbarrier.arrive.shared.b64 _, [%0];" :: "r"(mbar) : "memory");
}
__device__ __forceinline__ void mbar_expect_tx(uint32_t mbar, uint32_t bytes) {
    asm volatile("mbarrier.arrive.expect_tx.shared.b64 _, [%0], %1;"
                 :: "r"(mbar), "r"(bytes) : "memory");
}
__device__ __forceinline__ void mbar_wait(uint32_t mbar, uint32_t parity) {
    asm volatile(
        "{\n\t.reg .pred P;\n\t"
        "WL%=:\n\t"
        "mbarrier.try_wait.parity.acquire.cta.shared::cta.b64 P, [%0], %1, 0x989680;\n\t"
        "@!P bra WL%=;\n\t}"
        :: "r"(mbar), "r"(parity) : "memory");
}
// store v into peer CTA smem [raddr], auto-arriving 4 tx bytes on peer's [rmbar]
__device__ __forceinline__ void st_async_f32(uint32_t raddr, float v, uint32_t rmbar) {
    asm volatile(
        "st.async.shared::cluster.mbarrier::complete_tx::bytes.f32 [%0], %1, [%2];"
        :: "r"(raddr), "f"(v), "r"(rmbar) : "memory");
}
// tanh via exp: exact saturation at +-1, rel err ~1e-6, ~2 MUFU ops
__device__ __forceinline__ float tanh_fast(float x) {
    float e = __expf(2.0f * x);
    return 1.0f - __fdividef(2.0f, e + 1.0f);
}

// ---------------------------------------------------------------------------
// Kernel 1: xw[b,s,h] = x[b,s,:] . Wx_w[h,:] + Wx_b[h]  (into outputs region)
// ---------------------------------------------------------------------------
__global__ __launch_bounds__(256, 2)
void xw_gemm_kernel(const float* __restrict__ A, const float* __restrict__ W,
                    const float* __restrict__ bias, float* __restrict__ C) {
    __shared__ __align__(16) float As[16][128];
    __shared__ __align__(16) float Bs[16][128];

    const int tid = threadIdx.x;
    const int tx = tid & 15;
    const int ty = tid >> 4;
    const long bm = (long)blockIdx.x * 128;
    const long bn = (long)blockIdx.y * 128;

    const float* Ab = A + bm * I_DIM;
    const float* Wb = W + bn * I_DIM;

    unsigned long long acc[8][4];
#pragma unroll
    for (int i = 0; i < 8; i++)
#pragma unroll
        for (int j = 0; j < 4; j++) acc[i][j] = 0ull;

    for (int k0 = 0; k0 < I_DIM; k0 += 16) {
#pragma unroll
        for (int f = tid; f < 512; f += 256) {
            int row = f >> 2, kq = f & 3;
            float4 va = *(const float4*)(Ab + (long)row * I_DIM + k0 + kq * 4);
            As[kq * 4 + 0][row] = va.x; As[kq * 4 + 1][row] = va.y;
            As[kq * 4 + 2][row] = va.z; As[kq * 4 + 3][row] = va.w;
            float4 vw = *(const float4*)(Wb + (long)row * I_DIM + k0 + kq * 4);
            Bs[kq * 4 + 0][row] = vw.x; Bs[kq * 4 + 1][row] = vw.y;
            Bs[kq * 4 + 2][row] = vw.z; Bs[kq * 4 + 3][row] = vw.w;
        }
        __syncthreads();
#pragma unroll
        for (int k = 0; k < 16; k++) {
            const float4* As4 = (const float4*)&As[k][0];
            const ulonglong2* Bs2 = (const ulonglong2*)&Bs[k][0];
            float4 a0 = As4[ty * 2], a1 = As4[ty * 2 + 1];
            ulonglong2 bA = Bs2[tx * 2], bB = Bs2[tx * 2 + 1];
            unsigned long long bp[4] = {bA.x, bA.y, bB.x, bB.y};
            float av[8] = {a0.x, a0.y, a0.z, a0.w, a1.x, a1.y, a1.z, a1.w};
#pragma unroll
            for (int i = 0; i < 8; i++) {
                unsigned long long ap = pack2(av[i], av[i]);
#pragma unroll
                for (int j = 0; j < 4; j++) acc[i][j] = ffma2(ap, bp[j], acc[i][j]);
            }
        }
        __syncthreads();
    }

    float bv[8];
#pragma unroll
    for (int j = 0; j < 8; j++) bv[j] = bias[bn + tx * 8 + j];
#pragma unroll
    for (int i = 0; i < 8; i++) {
        long m = bm + ty * 8 + i;
        float* Crow = C + m * (long)H_DIM + bn + tx * 8;
        float2 c0 = unpack2(acc[i][0]), c1 = unpack2(acc[i][1]);
        float2 c2 = unpack2(acc[i][2]), c3 = unpack2(acc[i][3]);
        *(float4*)(Crow)     = make_float4(c0.x + bv[0], c0.y + bv[1], c1.x + bv[2], c1.y + bv[3]);
        *(float4*)(Crow + 4) = make_float4(c2.x + bv[4], c2.y + bv[5], c3.x + bv[6], c3.y + bv[7]);
    }
}

// ---------------------------------------------------------------------------
// Kernel 2: recurrence. 2-CTA cluster per batch row; CTA rank r owns columns
// [128r,128r+128). Thread (jl,kc) holds 64 Wh weights in regs: 32 k from the
// LOCAL half + 32 k from the REMOTE half. Handshake: writers push h values
// straight into peer smem via st.async with mbarrier complete_tx; consumer
// does local-half FMAs, then a cheap local mbarrier try_wait, then the
// remote-half FMAs. Double buffered; one __syncthreads per step.
// ---------------------------------------------------------------------------
__global__ __launch_bounds__(512, 1) __cluster_dims__(2, 1, 1)
void srnn_recur_kernel(const float* __restrict__ Wh, float* __restrict__ out) {
    __shared__ __align__(16) float hL[2][128];   // my half (local writes)
    __shared__ __align__(16) float hR[2][128];   // peer half (st.async writes)
    __shared__ __align__(8) unsigned long long mbar[2];

    const int rank = blockIdx.x;
    const int row  = blockIdx.y;
    const int t    = threadIdx.x;
    const int jl   = t >> 2;          // 0..127 local output index
    const int kc   = t & 3;           // 0..3 k-chunk (32 k each per half)
    const int jg   = rank * 128 + jl; // global output column

    // --- preload weights (stagger-rotated to match smem read pattern) ---
    unsigned long long wlA[8], wlB[8], wrA[8], wrB[8];
    {
        const float* wL = Wh + (long)jg * H_DIM + (rank * 128 + kc * 32);
        const float* wR = Wh + (long)jg * H_DIM + ((rank ^ 1) * 128 + kc * 32);
#pragma unroll
        for (int u = 0; u < 8; u++) {
            int slot = (u + 2 * kc) & 7;
            ulonglong2 a = *(const ulonglong2*)(wL + slot * 4);
            wlA[u] = a.x; wlB[u] = a.y;
            ulonglong2 b = *(const ulonglong2*)(wR + slot * 4);
            wrA[u] = b.x; wrB[u] = b.y;
        }
    }

    const uint32_t mb0 = smem_u32(&mbar[0]);
    const uint32_t mb1 = smem_u32(&mbar[1]);

    if (t == 0) {
        mbar_init(mb0, 1);
        mbar_init(mb1, 1);
        mbar_arrive(mb0);            // mbar[0] phase 0: trivially complete (h0 known)
        mbar_expect_tx(mb1, 512);    // mbar[1] phase 0: armed for peer's step-0 stores
    }
    if (t < 128) { hL[0][t] = 0.0f; hR[0][t] = 0.0f; }
    __syncthreads();
    asm volatile("barrier.cluster.arrive.aligned;" ::: "memory");
    asm volatile("barrier.cluster.wait.aligned;" ::: "memory");

    // peer-CTA addresses for my output slot in both hR buffers + peer mbars
    const uint32_t prA0 = mapa_u32(smem_u32(&hR[0][jl]), rank ^ 1);
    const uint32_t prA1 = mapa_u32(smem_u32(&hR[1][jl]), rank ^ 1);
    const uint32_t pmb0 = mapa_u32(mb0, rank ^ 1);
    const uint32_t pmb1 = mapa_u32(mb1, rank ^ 1);

    float* xwp = out + (long)row * S_LEN * H_DIM + jg;
    float xw_next = (kc == 0) ? xwp[0] : 0.0f;

    for (int step = 0; step < S_LEN; step++) {
        const int p = step & 1;
        float xw_cur = xw_next;
        if (kc == 0 && step + 1 < S_LEN)
            xw_next = xwp[(long)(step + 1) * H_DIM];

        unsigned long long accA = 0ull, accB = 0ull;

        // ---- local half (no sync needed; hL[p] made visible by last step's bar)
        {
            const ulonglong2* h2 = (const ulonglong2*)&hL[p][kc * 32];
#pragma unroll
            for (int u = 0; u < 8; u++) {
                int slot = (u + 2 * kc) & 7;
                ulonglong2 hv = h2[slot];
                accA = ffma2(hv.x, wlA[u], accA);
                accB = ffma2(hv.y, wlB[u], accB);
            }
        }

        // ---- wait for peer half, then re-arm this mbar for its next use (step+2)
        const uint32_t mb = p ? mb1 : mb0;
        mbar_wait(mb, ((step - p) >> 1) & 1);
        if (t == 0) mbar_expect_tx(mb, 512);

        // ---- remote half
        {
            const ulonglong2* h2 = (const ulonglong2*)&hR[p][kc * 32];
#pragma unroll
            for (int u = 0; u < 8; u++) {
                int slot = (u + 2 * kc) & 7;
                ulonglong2 hv = h2[slot];
                accA = ffma2(hv.x, wrA[u], accA);
                accB = ffma2(hv.y, wrB[u], accB);
            }
        }

        float2 fA = unpack2(accA), fB = unpack2(accB);
        float s = (fA.x + fA.y) + (fB.x + fB.y);
        s += __shfl_xor_sync(0xffffffffu, s, 1);
        s += __shfl_xor_sync(0xffffffffu, s, 2);

        if (kc == 0) {
            float v = tanh_fast(s + xw_cur);
            hL[p ^ 1][jl] = v;
            st_async_f32(p ? prA0 : prA1, v, p ? pmb0 : pmb1);
            xwp[(long)step * H_DIM] = v;    // in-place output
            if (step == S_LEN - 1)
                out[(long)B_DIM * S_LEN * H_DIM + (long)row * H_DIM + jg] = v;
        }

        __syncthreads();  // hL[p^1] visible; all step-p reads done before reuse
    }

    // keep smem alive until peer's in-flight st.asyncs land
    asm volatile("barrier.cluster.arrive.aligned;" ::: "memory");
    asm volatile("barrier.cluster.wait.aligned;" ::: "memory");
}

// ---------------------------------------------------------------------------
// Launch
// ---------------------------------------------------------------------------
extern "C" void kernel_launch(void* const* d_in, const int* in_sizes, int n_in,
                              void* d_out, int out_size) {
    const float* x    = (const float*)d_in[0];  // [B,S,I]
    const float* Wx_w = (const float*)d_in[1];  // [H,I]
    const float* Wx_b = (const float*)d_in[2];  // [H]
    const float* Wh_w = (const float*)d_in[3];  // [H,H]
    float* out = (float*)d_out;                 // [B,S,H] ++ [B,H]

    dim3 g1((B_DIM * S_LEN) / 128, H_DIM / 128);
    xw_gemm_kernel<<<g1, 256>>>(x, Wx_w, Wx_b, out);

    dim3 g2(2, B_DIM);
    srnn_recur_kernel<<<g2, 512>>>(Wh_w, out);
}